// round 1
// baseline (speedup 1.0000x reference)
#include <cuda_runtime.h>
#include <cstdint>

// Problem constants
#define NGRAPH 128
#define NODES  256
#define CH     64
// Output layout (flattened pytree): adj_a, adj_b, adj_t, fa, fb, ft
#define ADJ_ELEMS   ((size_t)NGRAPH * NODES * NODES)   // 8388608
#define F_ELEMS     ((size_t)NGRAPH * NODES * CH)      // 2097152
#define F_BASE      (3 * ADJ_ELEMS)                    // 25165824

__device__ __forceinline__ uint32_t f2tf32(float x) {
    uint32_t u;
    asm("cvt.rna.tf32.f32 %0, %1;" : "=r"(u) : "f"(x));
    return u;
}

__device__ __forceinline__ void mma_tf32(float d[4], const uint32_t a[4], const uint32_t b[2]) {
    asm volatile(
        "mma.sync.aligned.m16n8k8.row.col.f32.tf32.tf32.f32 "
        "{%0,%1,%2,%3},{%4,%5,%6,%7},{%8,%9},{%0,%1,%2,%3};\n"
        : "+f"(d[0]), "+f"(d[1]), "+f"(d[2]), "+f"(d[3])
        : "r"(a[0]), "r"(a[1]), "r"(a[2]), "r"(a[3]),
          "r"(b[0]), "r"(b[1]));
}

__device__ __forceinline__ float sigmoid_fast(float x) {
    // 2 MUFU ops (EX2 + RCP), ~2-3 ulp — well under tolerance
    return __fdividef(1.0f, 1.0f + __expf(-x));
}

// ---------------------------------------------------------------------------
// Kernel 1: the three 2-layer MLPs, exact fp32.
// Block: 256 threads (16x16), tile = 64 rows x 64 cols, 4x4 microtile/thread.
// grid = (512 row-tiles, 3 types)
// ---------------------------------------------------------------------------
__global__ void __launch_bounds__(256) mlp3_kernel(
    const float* __restrict__ z,
    const float* __restrict__ Wa1, const float* __restrict__ ba1,
    const float* __restrict__ Wa2, const float* __restrict__ ba2,
    const float* __restrict__ Wb1, const float* __restrict__ bb1,
    const float* __restrict__ Wb2, const float* __restrict__ bb2,
    const float* __restrict__ Wt1, const float* __restrict__ bt1,
    const float* __restrict__ Wt2, const float* __restrict__ bt2,
    float* __restrict__ out)
{
    __shared__ __align__(16) float sZt[64 * 68];  // transposed activations [k][row], stride 68
    __shared__ __align__(16) float sW[64 * 64];   // weight [k][n]
    __shared__ float sb[64];

    const int type = blockIdx.y;
    const float *W1, *B1, *W2, *B2;
    if (type == 0)      { W1 = Wa1; B1 = ba1; W2 = Wa2; B2 = ba2; }
    else if (type == 1) { W1 = Wb1; B1 = bb1; W2 = Wb2; B2 = bb2; }
    else                { W1 = Wt1; B1 = bt1; W2 = Wt2; B2 = bt2; }

    float* __restrict__ fout = out + F_BASE + (size_t)type * F_ELEMS;

    const int rbase = blockIdx.x * 64;
    const int tid = threadIdx.x;
    const int tx = tid & 15, ty = tid >> 4;

    // Load z tile transposed into shared (coalesced global reads)
    for (int i = tid; i < 64 * 64; i += 256) {
        int r = i >> 6, c = i & 63;
        sZt[c * 68 + r] = z[(size_t)(rbase + r) * 64 + c];
    }
    // Load W1, b1
    for (int i = tid; i < 1024; i += 256)
        *(float4*)&sW[i * 4] = *(const float4*)&W1[i * 4];
    if (tid < 64) sb[tid] = B1[tid];
    __syncthreads();

    // ---- Layer 1 ----
    float acc[4][4];
#pragma unroll
    for (int i = 0; i < 4; ++i)
#pragma unroll
        for (int j = 0; j < 4; ++j) acc[i][j] = 0.0f;

#pragma unroll 16
    for (int k = 0; k < 64; ++k) {
        float4 a = *(const float4*)&sZt[k * 68 + ty * 4];
        float4 b = *(const float4*)&sW[k * 64 + tx * 4];
        float av[4] = {a.x, a.y, a.z, a.w};
        float bv[4] = {b.x, b.y, b.z, b.w};
#pragma unroll
        for (int i = 0; i < 4; ++i)
#pragma unroll
            for (int j = 0; j < 4; ++j)
                acc[i][j] = fmaf(av[i], bv[j], acc[i][j]);
    }

    float h[4][4];
#pragma unroll
    for (int i = 0; i < 4; ++i)
#pragma unroll
        for (int j = 0; j < 4; ++j)
            h[i][j] = fmaxf(acc[i][j] + sb[tx * 4 + j], 0.0f);

    __syncthreads();  // everyone done reading sZt / sW / sb

    // Store h transposed into sZt (reuse), reload W2/b2
#pragma unroll
    for (int j = 0; j < 4; ++j) {
        float4 v = make_float4(h[0][j], h[1][j], h[2][j], h[3][j]);
        *(float4*)&sZt[(tx * 4 + j) * 68 + ty * 4] = v;
    }
    for (int i = tid; i < 1024; i += 256)
        *(float4*)&sW[i * 4] = *(const float4*)&W2[i * 4];
    if (tid < 64) sb[tid] = B2[tid];
    __syncthreads();

    // ---- Layer 2 ----
#pragma unroll
    for (int i = 0; i < 4; ++i)
#pragma unroll
        for (int j = 0; j < 4; ++j) acc[i][j] = 0.0f;

#pragma unroll 16
    for (int k = 0; k < 64; ++k) {
        float4 a = *(const float4*)&sZt[k * 68 + ty * 4];
        float4 b = *(const float4*)&sW[k * 64 + tx * 4];
        float av[4] = {a.x, a.y, a.z, a.w};
        float bv[4] = {b.x, b.y, b.z, b.w};
#pragma unroll
        for (int i = 0; i < 4; ++i)
#pragma unroll
            for (int j = 0; j < 4; ++j)
                acc[i][j] = fmaf(av[i], bv[j], acc[i][j]);
    }

#pragma unroll
    for (int i = 0; i < 4; ++i) {
        float4 v;
        v.x = fmaxf(acc[i][0] + sb[tx * 4 + 0], 0.0f);
        v.y = fmaxf(acc[i][1] + sb[tx * 4 + 1], 0.0f);
        v.z = fmaxf(acc[i][2] + sb[tx * 4 + 2], 0.0f);
        v.w = fmaxf(acc[i][3] + sb[tx * 4 + 3], 0.0f);
        *(float4*)&fout[(size_t)(rbase + ty * 4 + i) * 64 + tx * 4] = v;
    }
}

// ---------------------------------------------------------------------------
// Kernel 2: adjacency = sigmoid(F F^T) per (graph, type) via tf32 mma.sync.
// Block: 256 threads (8 warps), tile 128x128, K=64 in one pass.
// Warp layout 2x4 -> 64x32 warp tile -> 4x4 m16n8k8 mmas per k-step.
// grid = (4 output tiles, 128 graphs, 3 types)
// Shared stride 68 floats -> fragment LDS bank = (4g + q) mod 32, conflict-free.
// ---------------------------------------------------------------------------
__global__ void __launch_bounds__(256, 2) adj_kernel(
    const float* __restrict__ F0, const float* __restrict__ F1, const float* __restrict__ F2,
    float* __restrict__ out)
{
    extern __shared__ __align__(16) float smem[];
    float* sA = smem;              // [128][68]
    float* sB = smem + 128 * 68;   // [128][68]

    const int type = blockIdx.z;
    const int gph  = blockIdx.y;
    const int tm = blockIdx.x >> 1, tn = blockIdx.x & 1;
    const float* __restrict__ F =
        (type == 0 ? F0 : (type == 1 ? F1 : F2)) + (size_t)gph * (NODES * CH);

    const int tid = threadIdx.x;
    // Load both row-blocks, converting to tf32 (rna) once here.
    for (int i = tid; i < 128 * 16; i += 256) {
        int r = i >> 4, c4 = (i & 15) * 4;
        float4 va = *(const float4*)&F[(size_t)(tm * 128 + r) * CH + c4];
        float4 vb = *(const float4*)&F[(size_t)(tn * 128 + r) * CH + c4];
        va.x = __uint_as_float(f2tf32(va.x));
        va.y = __uint_as_float(f2tf32(va.y));
        va.z = __uint_as_float(f2tf32(va.z));
        va.w = __uint_as_float(f2tf32(va.w));
        vb.x = __uint_as_float(f2tf32(vb.x));
        vb.y = __uint_as_float(f2tf32(vb.y));
        vb.z = __uint_as_float(f2tf32(vb.z));
        vb.w = __uint_as_float(f2tf32(vb.w));
        *(float4*)&sA[r * 68 + c4] = va;
        *(float4*)&sB[r * 68 + c4] = vb;
    }
    __syncthreads();

    const int warp = tid >> 5, lane = tid & 31;
    const int g8 = lane >> 2, q = lane & 3;
    const int wm = (warp >> 2) * 64;   // 0 or 64
    const int wn = (warp & 3) * 32;    // 0..96

    float acc[4][4][4];
#pragma unroll
    for (int mt = 0; mt < 4; ++mt)
#pragma unroll
        for (int nt = 0; nt < 4; ++nt)
#pragma unroll
            for (int e = 0; e < 4; ++e) acc[mt][nt][e] = 0.0f;

#pragma unroll
    for (int k0 = 0; k0 < 8; ++k0) {
        const int kc = k0 * 8 + q;
        uint32_t af[4][4], bf[4][2];
#pragma unroll
        for (int mt = 0; mt < 4; ++mt) {
            const float* p = &sA[(wm + mt * 16 + g8) * 68 + kc];
            af[mt][0] = __float_as_uint(p[0]);
            af[mt][2] = __float_as_uint(p[4]);
            af[mt][1] = __float_as_uint(p[8 * 68]);
            af[mt][3] = __float_as_uint(p[8 * 68 + 4]);
        }
#pragma unroll
        for (int nt = 0; nt < 4; ++nt) {
            const float* p = &sB[(wn + nt * 8 + g8) * 68 + kc];
            bf[nt][0] = __float_as_uint(p[0]);
            bf[nt][1] = __float_as_uint(p[4]);
        }
#pragma unroll
        for (int mt = 0; mt < 4; ++mt)
#pragma unroll
            for (int nt = 0; nt < 4; ++nt)
                mma_tf32(acc[mt][nt], af[mt], bf[nt]);
    }

    float* __restrict__ O = out + ((size_t)type * NGRAPH + gph) * (NODES * NODES);
#pragma unroll
    for (int mt = 0; mt < 4; ++mt) {
        int row = tm * 128 + wm + mt * 16 + g8;
#pragma unroll
        for (int nt = 0; nt < 4; ++nt) {
            int col = tn * 128 + wn + nt * 8 + 2 * q;
            float2 v0, v1;
            v0.x = sigmoid_fast(acc[mt][nt][0]);
            v0.y = sigmoid_fast(acc[mt][nt][1]);
            v1.x = sigmoid_fast(acc[mt][nt][2]);
            v1.y = sigmoid_fast(acc[mt][nt][3]);
            *(float2*)&O[(size_t)row * NODES + col] = v0;
            *(float2*)&O[(size_t)(row + 8) * NODES + col] = v1;
        }
    }
}

extern "C" void kernel_launch(void* const* d_in, const int* in_sizes, int n_in,
                              void* d_out, int out_size) {
    const float* z   = (const float*)d_in[0];
    // d_in[1] = batch (int64) -> uniform segments, unused
    const float* Wa1 = (const float*)d_in[2];
    const float* ba1 = (const float*)d_in[3];
    const float* Wa2 = (const float*)d_in[4];
    const float* ba2 = (const float*)d_in[5];
    const float* Wb1 = (const float*)d_in[6];
    const float* bb1 = (const float*)d_in[7];
    const float* Wb2 = (const float*)d_in[8];
    const float* bb2 = (const float*)d_in[9];
    const float* Wt1 = (const float*)d_in[10];
    const float* bt1 = (const float*)d_in[11];
    const float* Wt2 = (const float*)d_in[12];
    const float* bt2 = (const float*)d_in[13];
    float* out = (float*)d_out;

    mlp3_kernel<<<dim3(512, 3, 1), 256>>>(
        z, Wa1, ba1, Wa2, ba2, Wb1, bb1, Wb2, bb2, Wt1, bt1, Wt2, bt2, out);

    const int adj_smem = 2 * 128 * 68 * (int)sizeof(float);  // 69632 B
    cudaFuncSetAttribute(adj_kernel, cudaFuncAttributeMaxDynamicSharedMemorySize, adj_smem);
    adj_kernel<<<dim3(4, NGRAPH, 3), 256, adj_smem>>>(
        out + F_BASE, out + F_BASE + F_ELEMS, out + F_BASE + 2 * F_ELEMS, out);
}

// round 3
// speedup vs baseline: 1.3750x; 1.3750x over previous
#include <cuda_runtime.h>
#include <cstdint>

// Problem constants
#define NGRAPH 128
#define NODES  256
#define CH     64
#define ADJ_ELEMS   ((size_t)NGRAPH * NODES * NODES)   // 8388608
#define F_ELEMS     ((size_t)NGRAPH * NODES * CH)      // 2097152
#define F_BASE      (3 * ADJ_ELEMS)                    // 25165824
#define STR 68   // smem row stride (floats): (4*g8+q) bank pattern, conflict-free

__device__ __forceinline__ float tf32r(float x) {
    uint32_t u;
    asm("cvt.rna.tf32.f32 %0, %1;" : "=r"(u) : "f"(x));
    return __uint_as_float(u);
}

__device__ __forceinline__ void mma_tf32(float d[4], const uint32_t a[4], const uint32_t b[2]) {
    asm volatile(
        "mma.sync.aligned.m16n8k8.row.col.f32.tf32.tf32.f32 "
        "{%0,%1,%2,%3},{%4,%5,%6,%7},{%8,%9},{%0,%1,%2,%3};\n"
        : "+f"(d[0]), "+f"(d[1]), "+f"(d[2]), "+f"(d[3])
        : "r"(a[0]), "r"(a[1]), "r"(a[2]), "r"(a[3]),
          "r"(b[0]), "r"(b[1]));
}

__device__ __forceinline__ float sigmoid_fast(float x) {
    return __fdividef(1.0f, 1.0f + __expf(-x));
}

// ---------------------------------------------------------------------------
// Fully fused: per CTA = one (type, graph).
//   Phase 0: load z tile (fp32) + split weights to tf32 hi/lo in smem
//   Phase 1: 2-layer MLP via 3xTF32 mma, warp-private 16-row ownership,
//            in-place activation buffer, no block syncs
//   Phase 2: F -> gmem (fp32) and smem (tf32-rounded), inside layer-2 epilogue
//   Phase 3: adjacency sigmoid(F F^T) 256x256 via tf32 mma,
//            two 128-row halves to bound acc registers
// 512 threads, 139.8 KB dyn smem, grid (128,3) = 384 CTAs, ~2.6 waves
// ---------------------------------------------------------------------------
__global__ void __launch_bounds__(512, 1) fused_kernel(
    const float* __restrict__ z,
    const float* __restrict__ Wa1, const float* __restrict__ ba1,
    const float* __restrict__ Wa2, const float* __restrict__ ba2,
    const float* __restrict__ Wb1, const float* __restrict__ bb1,
    const float* __restrict__ Wb2, const float* __restrict__ bb2,
    const float* __restrict__ Wt1, const float* __restrict__ bt1,
    const float* __restrict__ Wt2, const float* __restrict__ bt2,
    float* __restrict__ out)
{
    extern __shared__ __align__(16) float smem[];
    float* sF   = smem;                       // [256][STR] z -> h -> F(tf32)
    float* sWhi = smem + 256 * STR;           // [2][64][STR]
    float* sWlo = sWhi + 2 * 64 * STR;        // [2][64][STR]
    float* sBias = sWlo + 2 * 64 * STR;       // [128]

    const int g    = blockIdx.x;
    const int type = blockIdx.y;

    const float *W1, *B1, *W2, *B2;
    if (type == 0)      { W1 = Wa1; B1 = ba1; W2 = Wa2; B2 = ba2; }
    else if (type == 1) { W1 = Wb1; B1 = bb1; W2 = Wb2; B2 = bb2; }
    else                { W1 = Wt1; B1 = bt1; W2 = Wt2; B2 = bt2; }

    const int tid = threadIdx.x;
    const int warp = tid >> 5, lane = tid & 31;
    const int g8 = lane >> 2, q = lane & 3;

    // ---------------- Phase 0: loads ----------------
    const float* zG = z + (size_t)g * NODES * CH;
    for (int i = tid; i < NODES * CH / 4; i += 512) {       // 4096 float4s
        int r = i >> 4, c4 = (i & 15) * 4;
        *(float4*)&sF[r * STR + c4] = *(const float4*)&zG[r * CH + c4];
    }
#pragma unroll 1
    for (int l = 0; l < 2; ++l) {
        const float* W = l ? W2 : W1;
        float* whi = sWhi + l * 64 * STR;
        float* wlo = sWlo + l * 64 * STR;
        for (int i = tid; i < 64 * 64; i += 512) {
            int k = i >> 6, n = i & 63;
            float w = W[k * 64 + n];            // coalesced read
            float hi = tf32r(w);
            whi[n * STR + k] = hi;              // transposed: [n][k]
            wlo[n * STR + k] = tf32r(w - hi);
        }
    }
    if (tid < 64)       sBias[tid] = B1[tid];
    else if (tid < 128) sBias[tid] = B2[tid - 64];
    __syncthreads();

    // ---------------- Phase 1: MLP (warp-private rows) ----------------
    const int row0 = warp * 16;  // each warp owns rows [row0, row0+16)
    float* __restrict__ fout = out + F_BASE + (size_t)type * F_ELEMS
                                   + (size_t)g * NODES * CH;

#pragma unroll 1
    for (int l = 0; l < 2; ++l) {
        const float* Whi  = sWhi + l * 64 * STR;
        const float* Wlo  = sWlo + l * 64 * STR;
        const float* bias = sBias + l * 64;

        float acc[8][4];
#pragma unroll
        for (int nt = 0; nt < 8; ++nt)
#pragma unroll
            for (int e = 0; e < 4; ++e) acc[nt][e] = 0.0f;

#pragma unroll
        for (int k0 = 0; k0 < 8; ++k0) {
            const int kc = k0 * 8 + q;
            float a0 = sF[(row0 + g8)     * STR + kc];
            float a1 = sF[(row0 + g8 + 8) * STR + kc];
            float a2 = sF[(row0 + g8)     * STR + kc + 4];
            float a3 = sF[(row0 + g8 + 8) * STR + kc + 4];
            float h0 = tf32r(a0), h1 = tf32r(a1), h2 = tf32r(a2), h3 = tf32r(a3);
            uint32_t ahi[4] = {__float_as_uint(h0), __float_as_uint(h1),
                               __float_as_uint(h2), __float_as_uint(h3)};
            uint32_t alo[4] = {__float_as_uint(tf32r(a0 - h0)), __float_as_uint(tf32r(a1 - h1)),
                               __float_as_uint(tf32r(a2 - h2)), __float_as_uint(tf32r(a3 - h3))};
#pragma unroll
            for (int nt = 0; nt < 8; ++nt) {
                const int bo = (nt * 8 + g8) * STR + kc;
                uint32_t bhi[2] = {__float_as_uint(Whi[bo]), __float_as_uint(Whi[bo + 4])};
                uint32_t blo[2] = {__float_as_uint(Wlo[bo]), __float_as_uint(Wlo[bo + 4])};
                mma_tf32(acc[nt], ahi, bhi);
                mma_tf32(acc[nt], alo, bhi);
                mma_tf32(acc[nt], ahi, blo);
            }
        }
        __syncwarp();   // all lanes done reading this warp's sF rows

#pragma unroll
        for (int nt = 0; nt < 8; ++nt) {
            const int c0 = nt * 8 + 2 * q;
            float v0 = fmaxf(acc[nt][0] + bias[c0],     0.0f);
            float v1 = fmaxf(acc[nt][1] + bias[c0 + 1], 0.0f);
            float v2 = fmaxf(acc[nt][2] + bias[c0],     0.0f);
            float v3 = fmaxf(acc[nt][3] + bias[c0 + 1], 0.0f);
            if (l == 0) {
                // hidden layer: keep full fp32 in smem
                *(float2*)&sF[(row0 + g8)     * STR + c0] = make_float2(v0, v1);
                *(float2*)&sF[(row0 + g8 + 8) * STR + c0] = make_float2(v2, v3);
            } else {
                // F: fp32 -> gmem, tf32-rounded -> smem (adjacency operand)
                *(float2*)&fout[(size_t)(row0 + g8)     * CH + c0] = make_float2(v0, v1);
                *(float2*)&fout[(size_t)(row0 + g8 + 8) * CH + c0] = make_float2(v2, v3);
                *(float2*)&sF[(row0 + g8)     * STR + c0] = make_float2(tf32r(v0), tf32r(v1));
                *(float2*)&sF[(row0 + g8 + 8) * STR + c0] = make_float2(tf32r(v2), tf32r(v3));
            }
        }
        __syncwarp();   // stores visible before next layer's lane-crossed reads
    }
    __syncthreads();    // full F (tf32) visible to all warps

    // ---------------- Phase 3: adjacency ----------------
    const int wm2 = warp >> 3;          // 0..1 -> 64-row block within half
    const int wn  = (warp & 7) * 32;    // 0..224
    float* __restrict__ O = out + ((size_t)type * NGRAPH + g) * (NODES * NODES);

#pragma unroll 1
    for (int hm = 0; hm < 2; ++hm) {
        const int rbase = hm * 128 + wm2 * 64;

        float acc[4][4][4];
#pragma unroll
        for (int mt = 0; mt < 4; ++mt)
#pragma unroll
            for (int nt = 0; nt < 4; ++nt)
#pragma unroll
                for (int e = 0; e < 4; ++e) acc[mt][nt][e] = 0.0f;

#pragma unroll
        for (int k0 = 0; k0 < 8; ++k0) {
            const int kc = k0 * 8 + q;
            uint32_t af[4][4], bf[4][2];
#pragma unroll
            for (int mt = 0; mt < 4; ++mt) {
                const float* p = &sF[(rbase + mt * 16 + g8) * STR + kc];
                af[mt][0] = __float_as_uint(p[0]);
                af[mt][2] = __float_as_uint(p[4]);
                af[mt][1] = __float_as_uint(p[8 * STR]);
                af[mt][3] = __float_as_uint(p[8 * STR + 4]);
            }
#pragma unroll
            for (int nt = 0; nt < 4; ++nt) {
                const float* p = &sF[(wn + nt * 8 + g8) * STR + kc];
                bf[nt][0] = __float_as_uint(p[0]);
                bf[nt][1] = __float_as_uint(p[4]);
            }
#pragma unroll
            for (int mt = 0; mt < 4; ++mt)
#pragma unroll
                for (int nt = 0; nt < 4; ++nt)
                    mma_tf32(acc[mt][nt], af[mt], bf[nt]);
        }

#pragma unroll
        for (int mt = 0; mt < 4; ++mt) {
            const int row = rbase + mt * 16 + g8;
#pragma unroll
            for (int nt = 0; nt < 4; ++nt) {
                const int col = wn + nt * 8 + 2 * q;
                float2 v0, v1;
                v0.x = sigmoid_fast(acc[mt][nt][0]);
                v0.y = sigmoid_fast(acc[mt][nt][1]);
                v1.x = sigmoid_fast(acc[mt][nt][2]);
                v1.y = sigmoid_fast(acc[mt][nt][3]);
                *(float2*)&O[(size_t)row * NODES + col]       = v0;
                *(float2*)&O[(size_t)(row + 8) * NODES + col] = v1;
            }
        }
    }
}

extern "C" void kernel_launch(void* const* d_in, const int* in_sizes, int n_in,
                              void* d_out, int out_size) {
    const float* z   = (const float*)d_in[0];
    // d_in[1] = batch (int64): uniform segments, unused
    const float* Wa1 = (const float*)d_in[2];
    const float* ba1 = (const float*)d_in[3];
    const float* Wa2 = (const float*)d_in[4];
    const float* ba2 = (const float*)d_in[5];
    const float* Wb1 = (const float*)d_in[6];
    const float* bb1 = (const float*)d_in[7];
    const float* Wb2 = (const float*)d_in[8];
    const float* bb2 = (const float*)d_in[9];
    const float* Wt1 = (const float*)d_in[10];
    const float* bt1 = (const float*)d_in[11];
    const float* Wt2 = (const float*)d_in[12];
    const float* bt2 = (const float*)d_in[13];
    float* out = (float*)d_out;

    const int smem_bytes = (256 * STR + 4 * 64 * STR + 128) * (int)sizeof(float); // 139776
    cudaFuncSetAttribute(fused_kernel, cudaFuncAttributeMaxDynamicSharedMemorySize, smem_bytes);
    fused_kernel<<<dim3(NGRAPH, 3), 512, smem_bytes>>>(
        z, Wa1, ba1, Wa2, ba2, Wb1, bb1, Wb2, bb2, Wt1, bt1, Wt2, bt2, out);
}